// round 6
// baseline (speedup 1.0000x reference)
#include <cuda_runtime.h>
#include <stdint.h>

// Fused projection + greedy per-pixel NMS.
//   coords_grid: [N, M, 3, H, W] float32
//   anchor_P:    [N, 3, 4]       float32
//   out:         [N, H, W, 8]    -- written as FLOAT32 (index values cast to
//                                   float; dataset output dtype is float32)
#define TOPK 8

template <bool VEC_STORE>
__global__ __launch_bounds__(256)
void nms_coords_kernel(const float* __restrict__ coords,
                       const float* __restrict__ P,
                       float* __restrict__ out,
                       int HW, int M, int total)
{
    const int tid = blockIdx.x * 256 + threadIdx.x;
    if (tid >= total) return;
    const unsigned mask = __activemask();   // warp peers that passed the guard

    const int n   = tid / HW;
    const int pix = tid - n * HW;

    // Camera matrix for this image (12 floats, L2-broadcast)
    const float* Pn = P + n * 12;
    const float p00 = Pn[0], p01 = Pn[1], p02 = Pn[2],  p03 = Pn[3];
    const float p10 = Pn[4], p11 = Pn[5], p12 = Pn[6],  p13 = Pn[7];
    const float p20 = Pn[8], p21 = Pn[9], p22 = Pn[10], p23 = Pn[11];

    // coords[n][m][c][pix]: pix contiguous across the warp -> coalesced lines
    const long long plane = (long long)HW;
    const float* base = coords + (long long)n * M * 3 * plane + pix;

    // Register-resident NMS state (constant indices after unroll -> registers)
    float sx[TOPK], sy[TOPK];
    int   si[TOPK];
#pragma unroll
    for (int k = 0; k < TOPK; k++) { sx[k] = 1e9f; sy[k] = 1e9f; si[k] = 0; }
    int cnt = 0;

    for (int m = 0; m < M; m++) {
        const float* cm = base + (long long)m * 3 * plane;
        const float cx = cm[0];
        const float cy = cm[plane];
        const float cz = cm[2 * plane];

        // X = P[:, :3] @ c + P[:, 3]
        const float X0 = fmaf(p00, cx, fmaf(p01, cy, fmaf(p02, cz, p03)));
        const float X1 = fmaf(p10, cx, fmaf(p11, cy, fmaf(p12, cz, p13)));
        const float X2 = fmaf(p20, cx, fmaf(p21, cy, fmaf(p22, cz, p23)));
        const float z  = fmaxf(X2, 1e-6f);
        const float x  = X0 / z;           // match reference's divide exactly
        const float y  = X1 / z;

        // Suppression: min squared distance over all 8 slots.
        // Unfilled slots hold 1e9 -> d2 ~ 2e18, never suppresses (matches ref).
        float dmin = 3.402823e38f;
#pragma unroll
        for (int k = 0; k < TOPK; k++) {
            const float dx = sx[k] - x;
            const float dy = sy[k] - y;
            dmin = fminf(dmin, fmaf(dx, dx, dy * dy));
        }

        const bool keep = (dmin > 4.0f) && (cnt < TOPK);
        if (keep) {
#pragma unroll
            for (int k = 0; k < TOPK; k++) {
                if (cnt == k) { sx[k] = x; sy[k] = y; si[k] = m; }
            }
            cnt++;
        }

        // Warp early exit: once every active lane kept 8, the rest are no-ops
        // (reference's keep requires cnt < topk, so trailing m's can't write).
        if (__all_sync(mask, cnt >= TOPK)) break;
    }

    // OUTPUT AS FLOAT32: indices are small ints, exactly representable.
    if (VEC_STORE) {
        float4* o = reinterpret_cast<float4*>(out) + (long long)tid * 2;
        o[0] = make_float4((float)si[0], (float)si[1], (float)si[2], (float)si[3]);
        o[1] = make_float4((float)si[4], (float)si[5], (float)si[6], (float)si[7]);
    } else {
        float* o = out + (long long)tid * TOPK;
#pragma unroll
        for (int k = 0; k < TOPK; k++) o[k] = (float)si[k];
    }
}

extern "C" void kernel_launch(void* const* d_in, const int* in_sizes, int n_in,
                              void* d_out, int out_size)
{
    // coords = largest input, P = smallest (robust to metadata ordering).
    int ci = 0, pi = 0;
    for (int i = 1; i < n_in; i++) {
        if (in_sizes[i] > in_sizes[ci]) ci = i;
        if (in_sizes[i] < in_sizes[pi]) pi = i;
    }
    const float* coords = (const float*)d_in[ci];
    const float* P      = (const float*)d_in[pi];
    float* out          = (float*)d_out;

    // Shapes at runtime (in_sizes documented as element counts):
    //   anchor_P: [N,3,4]      -> N  = p_elems / 12
    //   out:      [N,H,W,8]    -> HW = out_size / (8*N)
    //   coords:   [N,M,3,H,W]  -> M  = coords_elems / (3*N*HW)
    const long long p_elems      = in_sizes[pi];
    const long long coords_elems = in_sizes[ci];
    const int N     = (int)(p_elems / 12);
    const int HW    = (int)(out_size / (TOPK * (long long)N));
    const int M     = (int)(coords_elems / (3LL * N * HW));
    const int total = N * HW;

    const int blocks = (total + 255) / 256;

    if ((((uintptr_t)d_out) & 15u) == 0) {
        nms_coords_kernel<true><<<blocks, 256>>>(coords, P, out, HW, M, total);
    } else {
        nms_coords_kernel<false><<<blocks, 256>>>(coords, P, out, HW, M, total);
    }
}